// round 17
// baseline (speedup 1.0000x reference)
#include <cuda_runtime.h>
#include <cuda_fp16.h>
#include <mma.h>
#include <cstdint>

using namespace nvcuda;

#define NN 50000
#define NP 50048            // NN padded to multiple of 64 (gemm tiles)
#define EE 1600000
#define FF 128
#define HH 256
#define NB ((NN + 255) / 256)   // 196 scan blocks

// ---------------- static device scratch (allocation-free rule) ----------------
__device__ __align__(16) float  g_bufA[(size_t)NP * HH];   // fp32 activations x
__device__ __align__(16) __half g_h[(size_t)NN * HH];      // fp16 mirror of x (gather src)
__device__ __align__(16) __half g_ha[(size_t)NP * HH];     // fp16 aggregated Sx (gemm A)
__device__ __align__(16) __half g_w16[3 * HH * HH + FF * HH]; // fp16 weights
__device__ float g_dinv[NN];
__device__ int   g_cnt[NN];
__device__ int   g_fill[NN];
__device__ int   g_rowptr[NN + 1];
__device__ int   g_part[NB];
__device__ int   g_col[EE];
__device__ float g_val[EE];
__device__ float g_acc[2];
__device__ int   g_not64;

__device__ __forceinline__ int edge_at(const void* edges, size_t idx) {
    if (g_not64) return ((const int*)edges)[idx];
    long long v = ((const long long*)edges)[idx];
    return (int)v;
}

// ---------------- setup kernels ----------------------------------------------
__global__ __launch_bounds__(256) void init_kernel() {
    int i = blockIdx.x * blockDim.x + threadIdx.x;
    if (i < NN) { g_dinv[i] = 1.0f; g_cnt[i] = 0; g_fill[i] = 0; }
    if (i == 0) { g_acc[0] = 0.f; g_acc[1] = 0.f; g_not64 = 0; }
}

__global__ __launch_bounds__(256) void detect_kernel(const void* edges) {
    int i = blockIdx.x * blockDim.x + threadIdx.x;   // EE divisible by 256
    long long v = ((const long long*)edges)[i];
    bool bad = (v < 0 || v >= NN);
    unsigned any = __ballot_sync(0xFFFFFFFFu, bad);
    if ((threadIdx.x & 31) == 0 && any) atomicOr(&g_not64, 1);
}

__global__ __launch_bounds__(256) void edge_count_kernel(
    const void* __restrict__ edges, const float* __restrict__ w) {
    int e = blockIdx.x * blockDim.x + threadIdx.x;
    if (e >= EE) return;
    int dst = edge_at(edges, (size_t)EE + e);
    if ((unsigned)dst >= NN) return;
    atomicAdd(&g_dinv[dst], w[e]);
    atomicAdd(&g_cnt[dst], 1);
}

// scan stage 1: per-block partial sums of g_cnt (+ fold rsqrt of dinv)
__global__ __launch_bounds__(256) void scan1_kernel() {
    __shared__ int red[256];
    int t = threadIdx.x;
    int i = blockIdx.x * 256 + t;
    int c = 0;
    if (i < NN) {
        c = g_cnt[i];
        g_dinv[i] = rsqrtf(g_dinv[i]);   // deg >= 1 always (self loop)
    }
    red[t] = c;
    __syncthreads();
#pragma unroll
    for (int off = 128; off; off >>= 1) {
        if (t < off) red[t] += red[t + off];
        __syncthreads();
    }
    if (t == 0) g_part[blockIdx.x] = red[0];
}

// scan stage 2: one block scans the NB partials (exclusive)
__global__ __launch_bounds__(256) void scan2_kernel() {
    __shared__ int sh[256];
    int t = threadIdx.x;
    int v = (t < NB) ? g_part[t] : 0;
    sh[t] = v;
    __syncthreads();
#pragma unroll
    for (int off = 1; off < 256; off <<= 1) {
        int x = sh[t];
        int add = (t >= off) ? sh[t - off] : 0;
        __syncthreads();
        sh[t] = x + add;
        __syncthreads();
    }
    if (t < NB) g_part[t] = sh[t] - v;   // exclusive
}

// scan stage 3: per-block local exclusive scan + global offset -> rowptr
__global__ __launch_bounds__(256) void scan3_kernel() {
    __shared__ int sh[256];
    int t = threadIdx.x;
    int i = blockIdx.x * 256 + t;
    int c = (i < NN) ? g_cnt[i] : 0;
    sh[t] = c;
    __syncthreads();
#pragma unroll
    for (int off = 1; off < 256; off <<= 1) {
        int x = sh[t];
        int add = (t >= off) ? sh[t - off] : 0;
        __syncthreads();
        sh[t] = x + add;
        __syncthreads();
    }
    int excl = sh[t] - c;
    int base = g_part[blockIdx.x];
    if (i < NN) g_rowptr[i] = base + excl;
    if (i == NN - 1) g_rowptr[NN] = base + excl + c;
}

__global__ __launch_bounds__(256) void fill_kernel(
    const void* __restrict__ edges, const float* __restrict__ w) {
    int e = blockIdx.x * blockDim.x + threadIdx.x;
    if (e >= EE) return;
    int src = edge_at(edges, e);
    int dst = edge_at(edges, (size_t)EE + e);
    if ((unsigned)src >= NN || (unsigned)dst >= NN) return;
    int pos = g_rowptr[dst] + atomicAdd(&g_fill[dst], 1);
    if ((unsigned)pos >= EE) return;
    g_col[pos] = src;
    g_val[pos] = g_dinv[src] * w[e] * g_dinv[dst];
}

__global__ __launch_bounds__(256) void cvt_node_kernel(const float* __restrict__ node) {
    int i = blockIdx.x * blockDim.x + threadIdx.x;
    if (i < NN * FF) g_h[i] = __float2half(node[i]);
}

__global__ __launch_bounds__(256) void cvt_w_kernel(const float* __restrict__ W1,
                                                    const float* __restrict__ Wc) {
    int i = blockIdx.x * blockDim.x + threadIdx.x;
    const int NW1 = FF * HH, NWC = 3 * HH * HH;
    if (i < NW1) g_w16[i] = __float2half(W1[i]);
    else if (i < NW1 + NWC) g_w16[i] = __float2half(Wc[i - NW1]);
}

// ---------------- SpMM: g_ha = S * g_h (fp16 gather, fp32 accum, fp16 out) ---
template <int P>
__global__ __launch_bounds__(P) void spmm_h_kernel() {
    const __half2* __restrict__ x = (const __half2*)g_h;
    __half2* __restrict__ y = (__half2*)g_ha;
    int n = blockIdx.x;
    int f = threadIdx.x;
    int s = g_rowptr[n], e = g_rowptr[n + 1];
    float d = g_dinv[n];
    float2 xs = __half22float2(x[(size_t)n * P + f]);
    float ax0 = d * d * xs.x, ay0 = d * d * xs.y;   // self-loop term
    float ax1 = 0.f, ay1 = 0.f, ax2 = 0.f, ay2 = 0.f, ax3 = 0.f, ay3 = 0.f;
    __shared__ int   scol[P];
    __shared__ float sval[P];
    for (int base = s; base < e; base += P) {
        int m = min(P, e - base);
        __syncthreads();
        if (f < m) {
            scol[f] = g_col[base + f];
            sval[f] = g_val[base + f];
        }
        __syncthreads();
        int j = 0;
        for (; j + 4 <= m; j += 4) {
            float2 v0 = __half22float2(x[(size_t)scol[j + 0] * P + f]);
            float2 v1 = __half22float2(x[(size_t)scol[j + 1] * P + f]);
            float2 v2 = __half22float2(x[(size_t)scol[j + 2] * P + f]);
            float2 v3 = __half22float2(x[(size_t)scol[j + 3] * P + f]);
            ax0 = fmaf(sval[j + 0], v0.x, ax0); ay0 = fmaf(sval[j + 0], v0.y, ay0);
            ax1 = fmaf(sval[j + 1], v1.x, ax1); ay1 = fmaf(sval[j + 1], v1.y, ay1);
            ax2 = fmaf(sval[j + 2], v2.x, ax2); ay2 = fmaf(sval[j + 2], v2.y, ay2);
            ax3 = fmaf(sval[j + 3], v3.x, ax3); ay3 = fmaf(sval[j + 3], v3.y, ay3);
        }
        for (; j < m; j++) {
            float2 v = __half22float2(x[(size_t)scol[j] * P + f]);
            ax0 = fmaf(sval[j], v.x, ax0); ay0 = fmaf(sval[j], v.y, ay0);
        }
    }
    y[(size_t)n * P + f] =
        __floats2half2_rn((ax0 + ax1) + (ax2 + ax3), (ay0 + ay1) + (ay2 + ay3));
}

// ---------------- fused GEMM + bias (+LN+residual+ReLU) + fp16 mirror --------
// tile 64x256, 8 warps (2 warp_m x 4 warp_n), warp 32x64, BK=32.
// mode 0: x = A@W + bias                     (layer 1; writes x + mirror)
// mode 1: x = relu(LN(A@W + bias) + x)       (conv; writes x + mirror)
// mode 2: as mode 1, but output feeds ONLY the mean pool: no global writes,
//         accumulate o . fcW into g_acc.
__global__ __launch_bounds__(256) void gemm_ln_kernel(
    int K, int woff, const float* __restrict__ bias,
    const float* __restrict__ gamma, const float* __restrict__ beta,
    const float* __restrict__ fcW, int mode) {
    const __half* __restrict__ A  = g_ha;
    const __half* __restrict__ Bh = g_w16 + woff;
    __shared__ alignas(16) unsigned char sm[38912];
    __half (*As)[40]  = (__half(*)[40])sm;              // 64 x 40 halves (5120 B)
    __half (*Bs)[264] = (__half(*)[264])(sm + 5120);    // 32 x 264 halves (16896 B)
    float (*S)[264]   = (float(*)[264])sm;              // 32 x 264 fp32 (reuse, 33792 B)
    float* pb = (float*)(sm + 33792);                   // bias[256]
    float* pg = pb + 256;                               // gamma[256]
    float* pp = pg + 256;                               // beta[256]
    float* pw0 = pp + 256;                              // fcW col 0
    float* pw1 = pw0 + 256;                             // fcW col 1

    int t = threadIdx.x;
    pb[t] = bias[t]; pg[t] = gamma[t]; pp[t] = beta[t];
    if (mode == 2) { pw0[t] = fcW[2 * t]; pw1[t] = fcW[2 * t + 1]; }

    int wid = t >> 5;
    int warp_m = wid & 1;        // 2 groups of 32 rows
    int warp_n = wid >> 1;       // 4 groups of 64 cols
    int row0 = blockIdx.x * 64;

    wmma::fragment<wmma::accumulator, 16, 16, 16, float> acc[2][4];
#pragma unroll
    for (int i = 0; i < 2; i++)
#pragma unroll
        for (int j = 0; j < 4; j++) wmma::fill_fragment(acc[i][j], 0.0f);

    int ar = t >> 2, ac = (t & 3) * 8;       // A: 64 rows x 32 halves
    int br = t >> 5, bc = (t & 31) * 8;      // B: 8 rows/pass x 256 cols, 4 passes
    bool aok = (row0 + ar) < NN;

    for (int k0 = 0; k0 < K; k0 += 32) {
        uint4 av = make_uint4(0u, 0u, 0u, 0u);
        if (aok) av = *(const uint4*)(A + (size_t)(row0 + ar) * K + k0 + ac);
        *(uint4*)&As[ar][ac] = av;
#pragma unroll
        for (int it = 0; it < 4; it++)
            *(uint4*)&Bs[br + 8 * it][bc] =
                *(const uint4*)(Bh + (size_t)(k0 + br + 8 * it) * HH + bc);
        __syncthreads();
#pragma unroll
        for (int ks = 0; ks < 2; ks++) {
            wmma::fragment<wmma::matrix_a, 16, 16, 16, __half, wmma::row_major> af[2];
            wmma::fragment<wmma::matrix_b, 16, 16, 16, __half, wmma::row_major> bf[4];
#pragma unroll
            for (int i = 0; i < 2; i++)
                wmma::load_matrix_sync(af[i], &As[warp_m * 32 + i * 16][ks * 16], 40);
#pragma unroll
            for (int j = 0; j < 4; j++)
                wmma::load_matrix_sync(bf[j], &Bs[ks * 16][warp_n * 64 + j * 16], 264);
#pragma unroll
            for (int i = 0; i < 2; i++)
#pragma unroll
                for (int j = 0; j < 4; j++)
                    wmma::mma_sync(acc[i][j], af[i], bf[j], acc[i][j]);
        }
        __syncthreads();
    }

    float pa0 = 0.f, pa1 = 0.f;    // pool partials (mode 2)

    // epilogue: two passes of 32 rows through S
#pragma unroll
    for (int p = 0; p < 2; p++) {
        if (warp_m == p) {
#pragma unroll
            for (int i = 0; i < 2; i++)
#pragma unroll
                for (int j = 0; j < 4; j++)
                    wmma::store_matrix_sync(&S[i * 16][warp_n * 64 + j * 16],
                                            acc[i][j], 264, wmma::mem_row_major);
        }
        __syncthreads();

        int lrow = t >> 3;           // 0..31
        int lane8 = t & 7;
        int grow = row0 + p * 32 + lrow;

        float4 v[8];
        float sum = 0.f, sq = 0.f;
#pragma unroll
        for (int i = 0; i < 8; i++) {
            int c = lane8 * 4 + i * 32;
            v[i] = *(float4*)&S[lrow][c];
            v[i].x += pb[c + 0]; v[i].y += pb[c + 1];
            v[i].z += pb[c + 2]; v[i].w += pb[c + 3];
            sum += (v[i].x + v[i].y) + (v[i].z + v[i].w);
            sq  += (v[i].x * v[i].x + v[i].y * v[i].y) +
                   (v[i].z * v[i].z + v[i].w * v[i].w);
        }
        if (mode) {
#pragma unroll
            for (int o = 4; o; o >>= 1) {
                sum += __shfl_down_sync(0xFFFFFFFFu, sum, o, 8);
                sq  += __shfl_down_sync(0xFFFFFFFFu, sq, o, 8);
            }
            sum = __shfl_sync(0xFFFFFFFFu, sum, 0, 8);
            sq  = __shfl_sync(0xFFFFFFFFu, sq, 0, 8);
            float mu  = sum * (1.0f / HH);
            float var = sq * (1.0f / HH) - mu * mu;
            var = fmaxf(var, 0.f);
            float rs = rsqrtf(var + 1e-5f);
            if (grow < NN) {
#pragma unroll
                for (int i = 0; i < 8; i++) {
                    int c = lane8 * 4 + i * 32;
                    float4 r = *(float4*)&g_bufA[(size_t)grow * HH + c];
                    float4 o;
                    o.x = fmaxf((v[i].x - mu) * rs * pg[c + 0] + pp[c + 0] + r.x, 0.f);
                    o.y = fmaxf((v[i].y - mu) * rs * pg[c + 1] + pp[c + 1] + r.y, 0.f);
                    o.z = fmaxf((v[i].z - mu) * rs * pg[c + 2] + pp[c + 2] + r.z, 0.f);
                    o.w = fmaxf((v[i].w - mu) * rs * pg[c + 3] + pp[c + 3] + r.w, 0.f);
                    if (mode == 1) {
                        *(float4*)&g_bufA[(size_t)grow * HH + c] = o;
                        __half2* hp = (__half2*)(g_h + (size_t)grow * HH + c);
                        hp[0] = __floats2half2_rn(o.x, o.y);
                        hp[1] = __floats2half2_rn(o.z, o.w);
                    } else {
                        pa0 += o.x * pw0[c + 0] + o.y * pw0[c + 1] +
                               o.z * pw0[c + 2] + o.w * pw0[c + 3];
                        pa1 += o.x * pw1[c + 0] + o.y * pw1[c + 1] +
                               o.z * pw1[c + 2] + o.w * pw1[c + 3];
                    }
                }
            }
        } else if (grow < NN) {
#pragma unroll
            for (int i = 0; i < 8; i++) {
                int c = lane8 * 4 + i * 32;
                *(float4*)&g_bufA[(size_t)grow * HH + c] = v[i];
                __half2* hp = (__half2*)(g_h + (size_t)grow * HH + c);
                hp[0] = __floats2half2_rn(v[i].x, v[i].y);
                hp[1] = __floats2half2_rn(v[i].z, v[i].w);
            }
        }
        __syncthreads();
    }

    if (mode == 2) {
#pragma unroll
        for (int o = 16; o; o >>= 1) {
            pa0 += __shfl_down_sync(0xFFFFFFFFu, pa0, o);
            pa1 += __shfl_down_sync(0xFFFFFFFFu, pa1, o);
        }
        if ((t & 31) == 0) {
            atomicAdd(&g_acc[0], pa0);
            atomicAdd(&g_acc[1], pa1);
        }
    }
}

__global__ __launch_bounds__(32) void finish_kernel(const float* __restrict__ fcb,
                                                    float* __restrict__ out) {
    if (threadIdx.x == 0) {
        out[0] = g_acc[0] * (1.0f / NN) + fcb[0];
        out[1] = g_acc[1] * (1.0f / NN) + fcb[1];
    }
}

// ---------------- launch ------------------------------------------------------
extern "C" void kernel_launch(void* const* d_in, const int* in_sizes, int n_in,
                              void* d_out, int out_size) {
    const float* node  = (const float*)d_in[0];
    const void*  edges = d_in[1];
    const float* eattr = (const float*)d_in[2];
    const float* W1    = (const float*)d_in[3];
    const float* b1    = (const float*)d_in[4];
    const float* Wc    = (const float*)d_in[5];
    const float* bc    = (const float*)d_in[6];
    const float* lng   = (const float*)d_in[7];
    const float* lnb   = (const float*)d_in[8];
    const float* fcW   = (const float*)d_in[9];
    const float* fcb   = (const float*)d_in[10];
    float* out = (float*)d_out;

    const int TB = 256;
    const int NW = FF * HH + 3 * HH * HH;
    init_kernel<<<(NN + TB - 1) / TB, TB>>>();
    detect_kernel<<<EE / TB, TB>>>(edges);
    edge_count_kernel<<<(EE + TB - 1) / TB, TB>>>(edges, eattr);
    scan1_kernel<<<NB, 256>>>();
    scan2_kernel<<<1, 256>>>();
    scan3_kernel<<<NB, 256>>>();
    fill_kernel<<<(EE + TB - 1) / TB, TB>>>(edges, eattr);
    cvt_node_kernel<<<(NN * FF + TB - 1) / TB, TB>>>(node);
    cvt_w_kernel<<<(NW + TB - 1) / TB, TB>>>(W1, Wc);

    const int GG = NP / 64;       // 782 blocks
    const int WOFFC = FF * HH;

    // layer 1: aggregate (fp16 gather, F=128), fused GEMM+bias
    spmm_h_kernel<FF / 2><<<NN, FF / 2>>>();
    gemm_ln_kernel<<<GG, 256>>>(FF, 0, b1, b1, b1, fcW, 0);

    // conv 0,1: fused GEMM+bias+LN+residual+ReLU (writes x + mirror)
    for (int i = 0; i < 2; i++) {
        spmm_h_kernel<HH / 2><<<NN, HH / 2>>>();
        gemm_ln_kernel<<<GG, 256>>>(HH, WOFFC + i * HH * HH, bc + i * HH,
                                    lng + i * HH, lnb + i * HH, fcW, 1);
    }
    // conv 2: fused GEMM+...+pool (no global activation writes)
    spmm_h_kernel<HH / 2><<<NN, HH / 2>>>();
    gemm_ln_kernel<<<GG, 256>>>(HH, WOFFC + 2 * HH * HH, bc + 2 * HH,
                                lng + 2 * HH, lnb + 2 * HH, fcW, 2);

    finish_kernel<<<1, 32>>>(fcb, out);
}